// round 12
// baseline (speedup 1.0000x reference)
#include <cuda_runtime.h>
#include <cuda_bf16.h>
#include <math.h>
#include <stdint.h>

#define NA   32
#define LA   32
#define BB   64
#define LBD  32
#define DIN  768
#define HD   768
#define MQ   (NA*LA)     // 1024
#define MKV  (BB*LBD)    // 2048
#define OT_INV_EPS 10.0f
#define INV768 (1.0f/768.0f)

typedef unsigned long long u64;
typedef __nv_bfloat16 bf16;

// ---------------- scratch (device globals; no allocation allowed) ----------
__device__ float g_q[MQ*HD];
__device__ float g_k[MKV*HD];
__device__ float g_v[MKV*HD];
__device__ float g_ecls[NA*HD];
__device__ float g_qinv[MQ];
__device__ float g_kinv[MKV];
__device__ float g_Tp[MQ*MKV];      // sinkhorn output, tile-packed
// bf16 hi/lo operands
__device__ __align__(16) bf16 g_qh[MQ*HD];
__device__ __align__(16) bf16 g_ql[MQ*HD];
__device__ __align__(16) bf16 g_kh[MKV*HD];
__device__ __align__(16) bf16 g_kl[MKV*HD];
__device__ __align__(16) bf16 g_eth[MQ*DIN],  g_etl[MQ*DIN];
__device__ __align__(16) bf16 g_mth[MKV*DIN], g_mtl[MKV*DIN];
__device__ __align__(16) bf16 g_ech[NA*DIN],  g_ecl[NA*DIN];
__device__ __align__(16) bf16 g_wqh[HD*DIN],  g_wql[HD*DIN];
__device__ __align__(16) bf16 g_wkh[HD*DIN],  g_wkl[HD*DIN];
__device__ __align__(16) bf16 g_wvh[HD*DIN],  g_wvl[HD*DIN];
__device__ __align__(16) bf16 g_wch[HD*DIN],  g_wcl[HD*DIN];

// ---------------- f32x2 packed-math helpers --------------------------------
__device__ __forceinline__ u64 dup2(float x) {
    u64 r; asm("mov.b64 %0, {%1, %1};" : "=l"(r) : "f"(x)); return r;
}
__device__ __forceinline__ void fma2(u64 &d, u64 a, u64 b) {
    asm("fma.rn.f32x2 %0, %1, %2, %0;" : "+l"(d) : "l"(a), "l"(b));
}
__device__ __forceinline__ float warp_sum(float x) {
#pragma unroll
    for (int o = 16; o > 0; o >>= 1) x += __shfl_xor_sync(0xffffffffu, x, o);
    return x;
}
__device__ __forceinline__ float warp_max(float x) {
#pragma unroll
    for (int o = 16; o > 0; o >>= 1) x = fmaxf(x, __shfl_xor_sync(0xffffffffu, x, o));
    return x;
}
__device__ __forceinline__ uint32_t smem_u32(const void* p) {
    uint32_t a;
    asm("{ .reg .u64 t; cvta.to.shared.u64 t, %1; cvt.u32.u64 %0, t; }"
        : "=r"(a) : "l"(p));
    return a;
}
__device__ __forceinline__ void ldsm4(uint32_t* r, uint32_t addr) {
    asm volatile("ldmatrix.sync.aligned.m8n8.x4.shared.b16 {%0,%1,%2,%3}, [%4];"
        : "=r"(r[0]), "=r"(r[1]), "=r"(r[2]), "=r"(r[3]) : "r"(addr));
}
__device__ __forceinline__ void mma_bf16(float* c, const uint32_t* a, const uint32_t* b) {
    asm volatile(
        "mma.sync.aligned.m16n8k16.row.col.f32.bf16.bf16.f32 "
        "{%0,%1,%2,%3}, {%4,%5,%6,%7}, {%8,%9}, {%0,%1,%2,%3};"
        : "+f"(c[0]), "+f"(c[1]), "+f"(c[2]), "+f"(c[3])
        : "r"(a[0]), "r"(a[1]), "r"(a[2]), "r"(a[3]), "r"(b[0]), "r"(b[1]));
}
#define CPA(sm, gm) \
    asm volatile("cp.async.ca.shared.global [%0], [%1], 16;" :: "r"(sm), "l"(gm))
#define CPA_COMMIT() asm volatile("cp.async.commit_group;" ::: "memory")
#define CPA_WAIT(n)  asm volatile("cp.async.wait_group %0;" :: "n"(n) : "memory")

__device__ __forceinline__ void split4(const float4 v, uint2& h, uint2& l) {
    unsigned short hb[4], lb[4];
    const float vv[4] = {v.x, v.y, v.z, v.w};
#pragma unroll
    for (int e = 0; e < 4; e++) {
        bf16 hh = __float2bfloat16(vv[e]);
        bf16 ll = __float2bfloat16(vv[e] - __bfloat162float(hh));
        hb[e] = *(unsigned short*)&hh;
        lb[e] = *(unsigned short*)&ll;
    }
    h.x = (uint32_t)hb[0] | ((uint32_t)hb[1] << 16);
    h.y = (uint32_t)hb[2] | ((uint32_t)hb[3] << 16);
    l.x = (uint32_t)lb[0] | ((uint32_t)lb[1] << 16);
    l.y = (uint32_t)lb[2] | ((uint32_t)lb[3] << 16);
}

// ---------------- shared GEMM mainloop (BM=BN=128, BK=32) -------------------
#define TILE_B   10240
#define BUF_B    40960
#define SMEM_MMA (2 * BUF_B)

__device__ __forceinline__ void issue_stage(
    const bf16* Ah, const bf16* Al, const bf16* Bh, const bf16* Bl,
    int aRow0, int aMax, int bRow0, uint32_t sbase, int k0, int buf, int tid)
{
#pragma unroll
    for (int i = 0; i < 8; i++) {
        const int c = tid + i * 256;
        const int tile = c >> 9, cc = c & 511, row = cc >> 2, ch = cc & 3;
        const bf16* src;
        if (tile == 0)      src = Ah + (size_t)min(aRow0 + row, aMax) * 768 + k0 + ch * 8;
        else if (tile == 1) src = Al + (size_t)min(aRow0 + row, aMax) * 768 + k0 + ch * 8;
        else if (tile == 2) src = Bh + (size_t)(bRow0 + row) * 768 + k0 + ch * 8;
        else                src = Bl + (size_t)(bRow0 + row) * 768 + k0 + ch * 8;
        const uint32_t dst = sbase + buf * BUF_B + tile * TILE_B + row * 80 + ch * 16;
        CPA(dst, src);
    }
    CPA_COMMIT();
}

__device__ __forceinline__ void compute_stage(
    uint32_t sbase, int buf, int lane, int wid, float acc[4][4][4])
{
    const int wm = (wid >> 2) * 64;
    const int wn = (wid & 3) * 32;
    const uint32_t b0 = sbase + buf * BUF_B;
#pragma unroll
    for (int kk = 0; kk < 2; kk++) {
        uint32_t ah[4][4], al[4][4], bh[2][4], bl[2][4];
        const int ak = kk * 16 + ((lane >> 4) << 3);
        const int arow = wm + (lane & 15);
#pragma unroll
        for (int mi = 0; mi < 4; mi++) {
            const uint32_t off = (uint32_t)((arow + mi * 16) * 80 + ak * 2);
            ldsm4(ah[mi], b0 + off);
            ldsm4(al[mi], b0 + TILE_B + off);
        }
        const int bk = kk * 16 + (((lane >> 3) & 1) << 3);
        const int brow = wn + ((lane >> 4) << 3) + (lane & 7);
#pragma unroll
        for (int ni = 0; ni < 2; ni++) {
            const uint32_t off = (uint32_t)((brow + ni * 16) * 80 + bk * 2);
            ldsm4(bh[ni], b0 + 2 * TILE_B + off);
            ldsm4(bl[ni], b0 + 3 * TILE_B + off);
        }
#pragma unroll
        for (int mi = 0; mi < 4; mi++)
#pragma unroll
            for (int nj = 0; nj < 4; nj++) {
                const int ni = nj >> 1, rs = (nj & 1) * 2;
                uint32_t bH[2] = {bh[ni][rs], bh[ni][rs + 1]};
                uint32_t bL[2] = {bl[ni][rs], bl[ni][rs + 1]};
                mma_bf16(acc[mi][nj], ah[mi], bH);
                mma_bf16(acc[mi][nj], ah[mi], bL);
                mma_bf16(acc[mi][nj], al[mi], bH);
            }
    }
}

__device__ __forceinline__ void mma_mainloop(
    const bf16* Ah, const bf16* Al, const bf16* Bh, const bf16* Bl,
    int aRow0, int aMax, int bRow0, char* smem, float acc[4][4][4],
    int tid, int lane, int wid)
{
    const uint32_t sbase = smem_u32(smem);
    issue_stage(Ah, Al, Bh, Bl, aRow0, aMax, bRow0, sbase, 0, 0, tid);
#pragma unroll 1
    for (int s = 0; s < 24; s++) {
        CPA_WAIT(0);
        __syncthreads();
        if (s < 23)
            issue_stage(Ah, Al, Bh, Bl, aRow0, aMax, bRow0, sbase,
                        (s + 1) * 32, (s + 1) & 1, tid);
        compute_stage(sbase, s & 1, lane, wid, acc);
    }
}

// ============================================================================
// input conversions
// ============================================================================
__global__ void split_inputs_kernel(const float* __restrict__ et,
                                    const float* __restrict__ mt,
                                    const float* __restrict__ ec)
{
    const float* src; bf16 *hp, *lp; int n;
    switch (blockIdx.z) {
        case 0: src = et; hp = g_eth; lp = g_etl; n = MQ * DIN;  break;
        case 1: src = mt; hp = g_mth; lp = g_mtl; n = MKV * DIN; break;
        default: src = ec; hp = g_ech; lp = g_ecl; n = NA * DIN; break;
    }
    const int idx = (blockIdx.x * 256 + threadIdx.x) * 4;
    if (idx >= n) return;
    uint2 h, l;
    split4(*(const float4*)&src[idx], h, l);
    *(uint2*)&hp[idx] = h;
    *(uint2*)&lp[idx] = l;
}

__global__ void __launch_bounds__(256) wtrans_kernel(
    const float* __restrict__ Wq, const float* __restrict__ Wk,
    const float* __restrict__ Wv, const float* __restrict__ Wc)
{
    __shared__ float s[64][65];
    const float* W; bf16 *hp, *lp;
    switch (blockIdx.z) {
        case 0: W = Wq; hp = g_wqh; lp = g_wql; break;
        case 1: W = Wk; hp = g_wkh; lp = g_wkl; break;
        case 2: W = Wv; hp = g_wvh; lp = g_wvl; break;
        default: W = Wc; hp = g_wch; lp = g_wcl; break;
    }
    const int k0 = blockIdx.y * 64, n0 = blockIdx.x * 64;
    const int tid = threadIdx.x;
#pragma unroll
    for (int p = 0; p < 16; p++) {
        const int row = p * 4 + (tid >> 6), col = tid & 63;
        s[row][col] = W[(size_t)(k0 + row) * HD + n0 + col];
    }
    __syncthreads();
#pragma unroll
    for (int p = 0; p < 4; p++) {
        const int c = tid + p * 256;
        const int orow = c >> 4, oc = (c & 15) * 4;
        float4 v = make_float4(s[oc][orow], s[oc + 1][orow], s[oc + 2][orow], s[oc + 3][orow]);
        uint2 h, l;
        split4(v, h, l);
        const size_t o = (size_t)(n0 + orow) * HD + k0 + oc;
        *(uint2*)&hp[o] = h;
        *(uint2*)&lp[o] = l;
    }
}

// ============================================================================
// projections via mma.sync: C = A @ W + bias (fp32 out, validated round 5/8)
// ============================================================================
__global__ void __launch_bounds__(256) proj_mma_kernel(
    const float* __restrict__ bq, const float* __restrict__ bk,
    const float* __restrict__ bv, const float* __restrict__ bc)
{
    extern __shared__ char smem[];
    const bf16 *Ah, *Al, *Bh, *Bl; const float* bias; float* C; int m0, M;
    const int y = blockIdx.y;
    if (y < 8)       { Ah = g_eth; Al = g_etl; Bh = g_wqh; Bl = g_wql; bias = bq; C = g_q;    m0 = y * 128;        M = MQ;  }
    else if (y < 24) { Ah = g_mth; Al = g_mtl; Bh = g_wkh; Bl = g_wkl; bias = bk; C = g_k;    m0 = (y - 8) * 128;  M = MKV; }
    else if (y < 40) { Ah = g_mth; Al = g_mtl; Bh = g_wvh; Bl = g_wvl; bias = bv; C = g_v;    m0 = (y - 24) * 128; M = MKV; }
    else             { Ah = g_ech; Al = g_ecl; Bh = g_wch; Bl = g_wcl; bias = bc; C = g_ecls; m0 = 0;              M = NA;  }
    const int n0 = blockIdx.x * 128;
    const int tid = threadIdx.x, lane = tid & 31, wid = tid >> 5;

    float acc[4][4][4] = {};
    mma_mainloop(Ah, Al, Bh, Bl, m0, M - 1, n0, smem, acc, tid, lane, wid);

    const int wm = (wid >> 2) * 64, wn = (wid & 3) * 32;
#pragma unroll
    for (int mi = 0; mi < 4; mi++) {
        const int r0 = m0 + wm + mi * 16 + (lane >> 2);
#pragma unroll
        for (int nj = 0; nj < 4; nj++) {
            const int col = n0 + wn + nj * 8 + (lane & 3) * 2;
            const float b0 = bias[col], b1 = bias[col + 1];
            if (r0 < M)
                *(float2*)&C[(size_t)r0 * HD + col] =
                    make_float2(acc[mi][nj][0] + b0, acc[mi][nj][1] + b1);
            if (r0 + 8 < M)
                *(float2*)&C[(size_t)(r0 + 8) * HD + col] =
                    make_float2(acc[mi][nj][2] + b0, acc[mi][nj][3] + b1);
        }
    }
}

// ============================================================================
// NT cosine GEMM + FUSED Sinkhorn (validated round 8)
// ============================================================================
__global__ void __launch_bounds__(256) ntexp_sinkhorn_kernel()
{
    extern __shared__ char smem[];
    const int m0 = blockIdx.y * 128, n0 = blockIdx.x * 128;
    const int tid = threadIdx.x, lane = tid & 31, wid = tid >> 5;

    float acc[4][4][4] = {};
    mma_mainloop(g_qh, g_ql, g_kh, g_kl, m0, MQ - 1, n0, smem, acc, tid, lane, wid);
    __syncthreads();

    float* st = (float*)smem;
    const int wm = (wid >> 2) * 64, wn = (wid & 3) * 32;
#pragma unroll
    for (int mi = 0; mi < 4; mi++) {
        const int rr0 = wm + mi * 16 + (lane >> 2);
        const float ai0 = g_qinv[m0 + rr0] * OT_INV_EPS;
        const float ai1 = g_qinv[m0 + rr0 + 8] * OT_INV_EPS;
#pragma unroll
        for (int nj = 0; nj < 4; nj++) {
            const int cl = wn + nj * 8 + (lane & 3) * 2;
            const float b0 = g_kinv[n0 + cl], b1 = g_kinv[n0 + cl + 1];
            const int tj = cl >> 5, j = cl & 31;
            {
                const int ti = rr0 >> 5, i = rr0 & 31;
                float* p = st + (ti * 4 + tj) * 1056 + i * 33 + j;
                p[0] = __expf(acc[mi][nj][0] * ai0 * b0);
                p[1] = __expf(acc[mi][nj][1] * ai0 * b1);
            }
            {
                const int rr1 = rr0 + 8;
                const int ti = rr1 >> 5, i = rr1 & 31;
                float* p = st + (ti * 4 + tj) * 1056 + i * 33 + j;
                p[0] = __expf(acc[mi][nj][2] * ai1 * b0);
                p[1] = __expf(acc[mi][nj][3] * ai1 * b1);
            }
        }
    }
    __syncthreads();

#pragma unroll 1
    for (int tt = 0; tt < 2; tt++) {
        const int t = wid + tt * 8;
        const int ti = t >> 2, tj = t & 3;
        const float* S = st + t * 1056;
        float Q[32], QT[32];
#pragma unroll
        for (int j = 0; j < 32; j++) Q[j]  = S[lane * 33 + j];
#pragma unroll
        for (int j = 0; j < 32; j++) QT[j] = S[j * 33 + lane];
        float v_all[32];
#pragma unroll
        for (int j = 0; j < 32; j++) v_all[j] = 1.0f;
#pragma unroll 1
        for (int it = 0; it < 10; it++) {
            float s = 0.f;
#pragma unroll
            for (int j = 0; j < 32; j++) s = fmaf(Q[j], v_all[j], s);
            const float u = __fdividef(1.0f, s);
#pragma unroll
            for (int j = 0; j < 32; j++) v_all[j] = __shfl_sync(0xffffffffu, u, j);
            float s2 = 0.f;
#pragma unroll
            for (int j = 0; j < 32; j++) s2 = fmaf(QT[j], v_all[j], s2);
            const float v = __fdividef(1.0f, s2);
#pragma unroll
            for (int j = 0; j < 32; j++) v_all[j] = __shfl_sync(0xffffffffu, v, j);
        }
        float n2 = 0.f;
#pragma unroll
        for (int j = 0; j < 32; j++) {
            Q[j] *= v_all[j];
            n2 = fmaf(Q[j], Q[j], n2);
        }
        const float sc = __fdividef(1.0f, fmaxf(sqrtf(n2), 1e-12f));
        const int tileg = (m0 / 32 + ti) * 64 + (n0 / 32 + tj);
        float* dst = g_Tp + (size_t)tileg * 1024 + lane * 32;
#pragma unroll
        for (int p = 0; p < 8; p++)
            *(float4*)&dst[p * 4] = make_float4(Q[p*4] * sc, Q[p*4+1] * sc,
                                                Q[p*4+2] * sc, Q[p*4+3] * sc);
    }
}

// ============================================================================
// row L2-norm inverse + bf16 hi/lo of q,k (validated round 8)
// ============================================================================
__global__ void rownorm_convert_kernel()
{
    int row = blockIdx.x * 8 + (threadIdx.x >> 5);
    int lane = threadIdx.x & 31;
    const float* x; float* inv; bf16 *hp, *lp;
    if (row < MQ) {
        x = g_q + (size_t)row * HD; inv = g_qinv + row;
        hp = g_qh + (size_t)row * HD; lp = g_ql + (size_t)row * HD;
    } else {
        int r2 = row - MQ;
        x = g_k + (size_t)r2 * HD; inv = g_kinv + r2;
        hp = g_kh + (size_t)r2 * HD; lp = g_kl + (size_t)r2 * HD;
    }
    float s = 0.f;
#pragma unroll
    for (int p = 0; p < 6; p++) {
        const int d = lane * 4 + p * 128;
        float4 v4 = *(const float4*)&x[d];
        s += v4.x * v4.x + v4.y * v4.y + v4.z * v4.z + v4.w * v4.w;
        uint2 h, l;
        split4(v4, h, l);
        *(uint2*)&hp[d] = h;
        *(uint2*)&lp[d] = l;
    }
    s = warp_sum(s);
    if (lane == 0) *inv = 1.0f / fmaxf(sqrtf(s), 1e-8f);
}

// ============================================================================
// attend: 4 pairs (same b, 4 consecutive a) per CTA; v_b staged in smem ONCE.
// T@v body = round-2-validated smem-v version; phases = round-8-validated.
// grid (64, 8); smem 207.9 KB -> 1 CTA/SM.
// ============================================================================
__global__ void __launch_bounds__(256, 1) attend4_kernel(
    const float* __restrict__ Tp, const float* __restrict__ q,
    const float* __restrict__ v, const float* __restrict__ ecls,
    const float* __restrict__ entity_cls, const float* __restrict__ mention_cls,
    const float* __restrict__ ln1_g, const float* __restrict__ ln1_b,
    const float* __restrict__ Wsp, const float* __restrict__ bsp,
    const float* __restrict__ ln2_g, const float* __restrict__ ln2_b,
    float* __restrict__ out)
{
    extern __shared__ float sm[];
    float* sv    = sm;             // 24576
    float* satt  = sv + 24576;     // 24576
    float* sTt   = satt + 24576;   // 1152
    float* sWsp  = sTt + 1152;     // 768
    float* spool = sWsp + 768;     // 768
    float* sS    = spool + 768;    // 32
    float* sW    = sS + 32;        // 32
    float* sred  = sW + 32;        // 64

    const int b = blockIdx.x;
    const int tid = threadIdx.x, lane = tid & 31, wid = tid >> 5;

    // ---- stage v_b once (round-2-validated)
    const float* vb = v + (size_t)b * 32 * HD;
    for (int t = tid; t < 6144; t += 256)
        *(float4*)&sv[t * 4] = *(const float4*)&vb[t * 4];
    for (int t = tid; t < 768; t += 256) sWsp[t] = Wsp[t];
    const float bsp0 = bsp[0];

#pragma unroll 1
    for (int pp = 0; pp < 4; pp++) {
        const int a = blockIdx.y * 4 + pp;
        __syncthreads();   // previous pair fully done (and sv/sWsp ready on pp=0)

        // ---- load T tile transposed
        const float* Tb = Tp + (size_t)(a * 64 + b) * 1024;
        for (int t = tid; t < 1024; t += 256) {
            int i = t >> 5, j = t & 31;
            sTt[j * 36 + i] = Tb[t];
        }
        __syncthreads();

        // ---- attended = T @ v_b + q_a (smem v, packed fma2; round-2 body)
        {
            const int i0 = (wid & 3) * 8;
            const int dbase0 = (wid >> 2) * 384 + lane * 4;
            const float* qa = q + (size_t)(a * 32) * HD;
#pragma unroll 1
            for (int c = 0; c < 3; c++) {
                const int d = dbase0 + c * 128;
                u64 acc[8][2];
#pragma unroll
                for (int ii = 0; ii < 8; ii++) {
                    ulonglong2 qv = *(const ulonglong2*)&qa[(i0 + ii) * HD + d];
                    acc[ii][0] = qv.x; acc[ii][1] = qv.y;
                }
#pragma unroll 8
                for (int j = 0; j < 32; j++) {
                    const ulonglong2 vv = *(const ulonglong2*)&sv[j * HD + d];
                    float4 t0 = *(const float4*)&sTt[j * 36 + i0];
                    float4 t1 = *(const float4*)&sTt[j * 36 + i0 + 4];
                    u64 td[8] = {dup2(t0.x), dup2(t0.y), dup2(t0.z), dup2(t0.w),
                                 dup2(t1.x), dup2(t1.y), dup2(t1.z), dup2(t1.w)};
#pragma unroll
                    for (int ii = 0; ii < 8; ii++) {
                        fma2(acc[ii][0], td[ii], vv.x);
                        fma2(acc[ii][1], td[ii], vv.y);
                    }
                }
#pragma unroll
                for (int ii = 0; ii < 8; ii++) {
                    ulonglong2 o; o.x = acc[ii][0]; o.y = acc[ii][1];
                    *(ulonglong2*)&satt[(i0 + ii) * HD + d] = o;
                }
            }
        }
        __syncthreads();

        // ---- LN1 per row + fused softpool score dot
#pragma unroll 1
        for (int rr = 0; rr < 4; rr++) {
            const int i = wid + rr * 8;
            float* row = &satt[i * HD];
            float s = 0.f, sq = 0.f;
#pragma unroll
            for (int p = 0; p < 6; p++) {
                float4 x = *(float4*)&row[lane * 4 + p * 128];
                s += x.x + x.y + x.z + x.w;
                sq += x.x * x.x + x.y * x.y + x.z * x.z + x.w * x.w;
            }
            s = warp_sum(s); sq = warp_sum(sq);
            const float mean = s * INV768;
            const float var = sq * INV768 - mean * mean;
            const float rstd = rsqrtf(var + 1e-5f);
            float sc = 0.f;
#pragma unroll
            for (int p = 0; p < 6; p++) {
                const int d = lane * 4 + p * 128;
                float4 x  = *(float4*)&row[d];
                float4 g  = *(const float4*)&ln1_g[d];
                float4 bb = *(const float4*)&ln1_b[d];
                float4 w4 = *(const float4*)&sWsp[d];
                float4 y;
                y.x = (x.x - mean) * rstd * g.x + bb.x;
                y.y = (x.y - mean) * rstd * g.y + bb.y;
                y.z = (x.z - mean) * rstd * g.z + bb.z;
                y.w = (x.w - mean) * rstd * g.w + bb.w;
                *(float4*)&row[d] = y;
                sc += y.x * w4.x + y.y * w4.y + y.z * w4.z + y.w * w4.w;
            }
            sc = warp_sum(sc);
            if (lane == 0) sS[i] = sc + bsp0;
        }
        __syncthreads();

        // ---- softmax over 32 token scores (warp 0)
        if (wid == 0) {
            float sval = sS[lane];
            float mx = warp_max(sval);
            float e = expf(sval - mx);
            float sum = warp_sum(e);
            sW[lane] = e / sum;
        }
        __syncthreads();

        // ---- pooled
        for (int d = tid; d < HD; d += 256) {
            float p = 0.f;
#pragma unroll
            for (int i = 0; i < 32; i++) p = fmaf(sW[i], satt[i * HD + d], p);
            spool[d] = p;
        }
        __syncthreads();

        // ---- LN2 block reduce
        float s = 0.f, sq = 0.f;
        for (int d = tid; d < HD; d += 256) {
            float x = spool[d];
            s += x; sq += x * x;
        }
        s = warp_sum(s); sq = warp_sum(sq);
        if (lane == 0) { sred[wid] = s; sred[8 + wid] = sq; }
        __syncthreads();
        if (tid == 0) {
            float ts = 0.f, tq = 0.f;
#pragma unroll
            for (int w = 0; w < 8; w++) { ts += sred[w]; tq += sred[8 + w]; }
            sred[16] = ts; sred[17] = tq;
        }
        __syncthreads();
        const float mean2 = sred[16] * INV768;
        const float var2 = sred[17] * INV768 - mean2 * mean2;
        const float rstd2 = rsqrtf(var2 + 1e-5f);

        // ---- g2l / g2g
        const float* ea  = ecls + (size_t)a * HD;
        const float* eca = entity_cls + (size_t)a * HD;
        const float* mcb = mention_cls + (size_t)b * HD;
        float g2l = 0.f, g2g = 0.f;
        for (int d = tid; d < HD; d += 256) {
            float ctx = (spool[d] - mean2) * rstd2 * ln2_g[d] + ln2_b[d];
            g2l = fmaf(ea[d], ctx, g2l);
            g2g = fmaf(eca[d], mcb[d], g2g);
        }
        g2l = warp_sum(g2l); g2g = warp_sum(g2g);
        __syncthreads();
        if (lane == 0) { sred[wid] = g2l; sred[8 + wid] = g2g; }
        __syncthreads();
        if (tid == 0) {
            float tl = 0.f, tg = 0.f;
#pragma unroll
            for (int w = 0; w < 8; w++) { tl += sred[w]; tg += sred[8 + w]; }
            out[b * NA + a] = 0.5f * (tl + tg);
        }
    }
}

// ---------------------------------------------------------------------------
extern "C" void kernel_launch(void* const* d_in, const int* in_sizes, int n_in,
                              void* d_out, int out_size)
{
    const float* entity_cls     = (const float*)d_in[0];
    const float* entity_tokens  = (const float*)d_in[1];
    const float* mention_cls    = (const float*)d_in[2];
    const float* mention_tokens = (const float*)d_in[3];
    const float* Wq   = (const float*)d_in[4];
    const float* bq   = (const float*)d_in[5];
    const float* Wk   = (const float*)d_in[6];
    const float* bk   = (const float*)d_in[7];
    const float* Wv   = (const float*)d_in[8];
    const float* bv   = (const float*)d_in[9];
    const float* ln1g = (const float*)d_in[10];
    const float* ln1b = (const float*)d_in[11];
    const float* Wcls = (const float*)d_in[12];
    const float* bcls = (const float*)d_in[13];
    const float* Wsp  = (const float*)d_in[14];
    const float* bsp  = (const float*)d_in[15];
    const float* ln2g = (const float*)d_in[16];
    const float* ln2b = (const float*)d_in[17];
    float* out = (float*)d_out;

    float *pq, *pv, *pecls, *pTp;
    cudaGetSymbolAddress((void**)&pq,    g_q);
    cudaGetSymbolAddress((void**)&pv,    g_v);
    cudaGetSymbolAddress((void**)&pecls, g_ecls);
    cudaGetSymbolAddress((void**)&pTp,   g_Tp);

    split_inputs_kernel<<<dim3(1536, 1, 3), 256>>>(entity_tokens, mention_tokens, entity_cls);
    wtrans_kernel<<<dim3(12, 12, 4), 256>>>(Wq, Wk, Wv, Wcls);

    cudaFuncSetAttribute(proj_mma_kernel, cudaFuncAttributeMaxDynamicSharedMemorySize, SMEM_MMA);
    proj_mma_kernel<<<dim3(6, 41), 256, SMEM_MMA>>>(bq, bk, bv, bcls);

    rownorm_convert_kernel<<<(MQ + MKV) / 8, 256>>>();

    cudaFuncSetAttribute(ntexp_sinkhorn_kernel, cudaFuncAttributeMaxDynamicSharedMemorySize, SMEM_MMA);
    ntexp_sinkhorn_kernel<<<dim3(16, 8), 256, SMEM_MMA>>>();

    const int smem_bytes = (24576 + 24576 + 1152 + 768 + 768 + 32 + 32 + 64) * 4;
    cudaFuncSetAttribute(attend4_kernel, cudaFuncAttributeMaxDynamicSharedMemorySize, smem_bytes);
    attend4_kernel<<<dim3(BB, 8), 256, smem_bytes>>>(
        pTp, pq, pv, pecls, entity_cls, mention_cls,
        ln1g, ln1b, Wsp, bsp, ln2g, ln2b, out);
}

// round 13
// speedup vs baseline: 1.9486x; 1.9486x over previous
#include <cuda_runtime.h>
#include <cuda_bf16.h>
#include <math.h>
#include <stdint.h>

#define NA   32
#define LA   32
#define BB   64
#define LBD  32
#define DIN  768
#define HD   768
#define MQ   (NA*LA)     // 1024
#define MKV  (BB*LBD)    // 2048
#define OT_INV_EPS 10.0f
#define INV768 (1.0f/768.0f)

typedef unsigned long long u64;
typedef __nv_bfloat16 bf16;

// ---------------- scratch (device globals; no allocation allowed) ----------
__device__ float g_q[MQ*HD];
__device__ float g_k[MKV*HD];
__device__ float g_v[MKV*HD];
__device__ float g_ecls[NA*HD];
__device__ float g_qinv[MQ];
__device__ float g_kinv[MKV];
__device__ float g_Tp[MQ*MKV];      // sinkhorn output, tile-packed
// bf16 hi/lo operands
__device__ __align__(16) bf16 g_qh[MQ*HD];
__device__ __align__(16) bf16 g_ql[MQ*HD];
__device__ __align__(16) bf16 g_kh[MKV*HD];
__device__ __align__(16) bf16 g_kl[MKV*HD];
__device__ __align__(16) bf16 g_eth[MQ*DIN],  g_etl[MQ*DIN];
__device__ __align__(16) bf16 g_mth[MKV*DIN], g_mtl[MKV*DIN];
__device__ __align__(16) bf16 g_ech[NA*DIN],  g_ecl[NA*DIN];
__device__ __align__(16) bf16 g_wqh[HD*DIN],  g_wql[HD*DIN];
__device__ __align__(16) bf16 g_wkh[HD*DIN],  g_wkl[HD*DIN];
__device__ __align__(16) bf16 g_wvh[HD*DIN],  g_wvl[HD*DIN];
__device__ __align__(16) bf16 g_wch[HD*DIN],  g_wcl[HD*DIN];

// ---------------- f32x2 packed-math helpers (attend kernel) ----------------
__device__ __forceinline__ u64 dup2(float x) {
    u64 r; asm("mov.b64 %0, {%1, %1};" : "=l"(r) : "f"(x)); return r;
}
__device__ __forceinline__ void fma2(u64 &d, u64 a, u64 b) {
    asm("fma.rn.f32x2 %0, %1, %2, %0;" : "+l"(d) : "l"(a), "l"(b));
}
__device__ __forceinline__ float warp_sum(float x) {
#pragma unroll
    for (int o = 16; o > 0; o >>= 1) x += __shfl_xor_sync(0xffffffffu, x, o);
    return x;
}
__device__ __forceinline__ float warp_max(float x) {
#pragma unroll
    for (int o = 16; o > 0; o >>= 1) x = fmaxf(x, __shfl_xor_sync(0xffffffffu, x, o));
    return x;
}

// ---------------- mma.sync / ldmatrix / cp.async helpers -------------------
__device__ __forceinline__ uint32_t smem_u32(const void* p) {
    uint32_t a;
    asm("{ .reg .u64 t; cvta.to.shared.u64 t, %1; cvt.u32.u64 %0, t; }"
        : "=r"(a) : "l"(p));
    return a;
}
__device__ __forceinline__ void ldsm4(uint32_t* r, uint32_t addr) {
    asm volatile("ldmatrix.sync.aligned.m8n8.x4.shared.b16 {%0,%1,%2,%3}, [%4];"
        : "=r"(r[0]), "=r"(r[1]), "=r"(r[2]), "=r"(r[3]) : "r"(addr));
}
__device__ __forceinline__ void mma_bf16(float* c, const uint32_t* a, const uint32_t* b) {
    asm volatile(
        "mma.sync.aligned.m16n8k16.row.col.f32.bf16.bf16.f32 "
        "{%0,%1,%2,%3}, {%4,%5,%6,%7}, {%8,%9}, {%0,%1,%2,%3};"
        : "+f"(c[0]), "+f"(c[1]), "+f"(c[2]), "+f"(c[3])
        : "r"(a[0]), "r"(a[1]), "r"(a[2]), "r"(a[3]), "r"(b[0]), "r"(b[1]));
}
#define CPA(sm, gm) \
    asm volatile("cp.async.ca.shared.global [%0], [%1], 16;" :: "r"(sm), "l"(gm))
#define CPA_COMMIT() asm volatile("cp.async.commit_group;" ::: "memory")
#define CPA_WAIT(n)  asm volatile("cp.async.wait_group %0;" :: "n"(n) : "memory")

__device__ __forceinline__ void split4(const float4 v, uint2& h, uint2& l) {
    unsigned short hb[4], lb[4];
    const float vv[4] = {v.x, v.y, v.z, v.w};
#pragma unroll
    for (int e = 0; e < 4; e++) {
        bf16 hh = __float2bfloat16(vv[e]);
        bf16 ll = __float2bfloat16(vv[e] - __bfloat162float(hh));
        hb[e] = *(unsigned short*)&hh;
        lb[e] = *(unsigned short*)&ll;
    }
    h.x = (uint32_t)hb[0] | ((uint32_t)hb[1] << 16);
    h.y = (uint32_t)hb[2] | ((uint32_t)hb[3] << 16);
    l.x = (uint32_t)lb[0] | ((uint32_t)lb[1] << 16);
    l.y = (uint32_t)lb[2] | ((uint32_t)lb[3] << 16);
}

// ---------------- shared GEMM mainloop (BM=BN=128, BK=32) -------------------
#define TILE_B   10240
#define BUF_B    40960
#define SMEM_MMA (2 * BUF_B)

__device__ __forceinline__ void issue_stage(
    const bf16* Ah, const bf16* Al, const bf16* Bh, const bf16* Bl,
    int aRow0, int aMax, int bRow0, uint32_t sbase, int k0, int buf, int tid)
{
#pragma unroll
    for (int i = 0; i < 8; i++) {
        const int c = tid + i * 256;
        const int tile = c >> 9, cc = c & 511, row = cc >> 2, ch = cc & 3;
        const bf16* src;
        if (tile == 0)      src = Ah + (size_t)min(aRow0 + row, aMax) * 768 + k0 + ch * 8;
        else if (tile == 1) src = Al + (size_t)min(aRow0 + row, aMax) * 768 + k0 + ch * 8;
        else if (tile == 2) src = Bh + (size_t)(bRow0 + row) * 768 + k0 + ch * 8;
        else                src = Bl + (size_t)(bRow0 + row) * 768 + k0 + ch * 8;
        const uint32_t dst = sbase + buf * BUF_B + tile * TILE_B + row * 80 + ch * 16;
        CPA(dst, src);
    }
    CPA_COMMIT();
}

__device__ __forceinline__ void compute_stage(
    uint32_t sbase, int buf, int lane, int wid, float acc[4][4][4])
{
    const int wm = (wid >> 2) * 64;
    const int wn = (wid & 3) * 32;
    const uint32_t b0 = sbase + buf * BUF_B;
#pragma unroll
    for (int kk = 0; kk < 2; kk++) {
        uint32_t ah[4][4], al[4][4], bh[2][4], bl[2][4];
        const int ak = kk * 16 + ((lane >> 4) << 3);
        const int arow = wm + (lane & 15);
#pragma unroll
        for (int mi = 0; mi < 4; mi++) {
            const uint32_t off = (uint32_t)((arow + mi * 16) * 80 + ak * 2);
            ldsm4(ah[mi], b0 + off);
            ldsm4(al[mi], b0 + TILE_B + off);
        }
        const int bk = kk * 16 + (((lane >> 3) & 1) << 3);
        const int brow = wn + ((lane >> 4) << 3) + (lane & 7);
#pragma unroll
        for (int ni = 0; ni < 2; ni++) {
            const uint32_t off = (uint32_t)((brow + ni * 16) * 80 + bk * 2);
            ldsm4(bh[ni], b0 + 2 * TILE_B + off);
            ldsm4(bl[ni], b0 + 3 * TILE_B + off);
        }
#pragma unroll
        for (int mi = 0; mi < 4; mi++)
#pragma unroll
            for (int nj = 0; nj < 4; nj++) {
                const int ni = nj >> 1, rs = (nj & 1) * 2;
                uint32_t bH[2] = {bh[ni][rs], bh[ni][rs + 1]};
                uint32_t bL[2] = {bl[ni][rs], bl[ni][rs + 1]};
                mma_bf16(acc[mi][nj], ah[mi], bH);
                mma_bf16(acc[mi][nj], ah[mi], bL);
                mma_bf16(acc[mi][nj], al[mi], bH);
            }
    }
}

__device__ __forceinline__ void mma_mainloop(
    const bf16* Ah, const bf16* Al, const bf16* Bh, const bf16* Bl,
    int aRow0, int aMax, int bRow0, char* smem, float acc[4][4][4],
    int tid, int lane, int wid)
{
    const uint32_t sbase = smem_u32(smem);
    issue_stage(Ah, Al, Bh, Bl, aRow0, aMax, bRow0, sbase, 0, 0, tid);
#pragma unroll 1
    for (int s = 0; s < 24; s++) {
        CPA_WAIT(0);
        __syncthreads();
        if (s < 23)
            issue_stage(Ah, Al, Bh, Bl, aRow0, aMax, bRow0, sbase,
                        (s + 1) * 32, (s + 1) & 1, tid);
        compute_stage(sbase, s & 1, lane, wid, acc);
    }
}

// ============================================================================
// input conversions
// ============================================================================
__global__ void split_inputs_kernel(const float* __restrict__ et,
                                    const float* __restrict__ mt,
                                    const float* __restrict__ ec)
{
    const float* src; bf16 *hp, *lp; int n;
    switch (blockIdx.z) {
        case 0: src = et; hp = g_eth; lp = g_etl; n = MQ * DIN;  break;
        case 1: src = mt; hp = g_mth; lp = g_mtl; n = MKV * DIN; break;
        default: src = ec; hp = g_ech; lp = g_ecl; n = NA * DIN; break;
    }
    const int idx = (blockIdx.x * 256 + threadIdx.x) * 4;
    if (idx >= n) return;
    uint2 h, l;
    split4(*(const float4*)&src[idx], h, l);
    *(uint2*)&hp[idx] = h;
    *(uint2*)&lp[idx] = l;
}

__global__ void __launch_bounds__(256) wtrans_kernel(
    const float* __restrict__ Wq, const float* __restrict__ Wk,
    const float* __restrict__ Wv, const float* __restrict__ Wc)
{
    __shared__ float s[64][65];
    const float* W; bf16 *hp, *lp;
    switch (blockIdx.z) {
        case 0: W = Wq; hp = g_wqh; lp = g_wql; break;
        case 1: W = Wk; hp = g_wkh; lp = g_wkl; break;
        case 2: W = Wv; hp = g_wvh; lp = g_wvl; break;
        default: W = Wc; hp = g_wch; lp = g_wcl; break;
    }
    const int k0 = blockIdx.y * 64, n0 = blockIdx.x * 64;
    const int tid = threadIdx.x;
#pragma unroll
    for (int p = 0; p < 16; p++) {
        const int row = p * 4 + (tid >> 6), col = tid & 63;
        s[row][col] = W[(size_t)(k0 + row) * HD + n0 + col];
    }
    __syncthreads();
#pragma unroll
    for (int p = 0; p < 4; p++) {
        const int c = tid + p * 256;
        const int orow = c >> 4, oc = (c & 15) * 4;
        float4 v = make_float4(s[oc][orow], s[oc + 1][orow], s[oc + 2][orow], s[oc + 3][orow]);
        uint2 h, l;
        split4(v, h, l);
        const size_t o = (size_t)(n0 + orow) * HD + k0 + oc;
        *(uint2*)&hp[o] = h;
        *(uint2*)&lp[o] = l;
    }
}

// ============================================================================
// projections via mma.sync: C = A @ W + bias (fp32 out, validated round 5/8)
// __launch_bounds__(256, 2): 2 CTAs/SM -> grid 246 fits one wave
// ============================================================================
__global__ void __launch_bounds__(256, 2) proj_mma_kernel(
    const float* __restrict__ bq, const float* __restrict__ bk,
    const float* __restrict__ bv, const float* __restrict__ bc)
{
    extern __shared__ char smem[];
    const bf16 *Ah, *Al, *Bh, *Bl; const float* bias; float* C; int m0, M;
    const int y = blockIdx.y;
    if (y < 8)       { Ah = g_eth; Al = g_etl; Bh = g_wqh; Bl = g_wql; bias = bq; C = g_q;    m0 = y * 128;        M = MQ;  }
    else if (y < 24) { Ah = g_mth; Al = g_mtl; Bh = g_wkh; Bl = g_wkl; bias = bk; C = g_k;    m0 = (y - 8) * 128;  M = MKV; }
    else if (y < 40) { Ah = g_mth; Al = g_mtl; Bh = g_wvh; Bl = g_wvl; bias = bv; C = g_v;    m0 = (y - 24) * 128; M = MKV; }
    else             { Ah = g_ech; Al = g_ecl; Bh = g_wch; Bl = g_wcl; bias = bc; C = g_ecls; m0 = 0;              M = NA;  }
    const int n0 = blockIdx.x * 128;
    const int tid = threadIdx.x, lane = tid & 31, wid = tid >> 5;

    float acc[4][4][4] = {};
    mma_mainloop(Ah, Al, Bh, Bl, m0, M - 1, n0, smem, acc, tid, lane, wid);

    const int wm = (wid >> 2) * 64, wn = (wid & 3) * 32;
#pragma unroll
    for (int mi = 0; mi < 4; mi++) {
        const int r0 = m0 + wm + mi * 16 + (lane >> 2);
#pragma unroll
        for (int nj = 0; nj < 4; nj++) {
            const int col = n0 + wn + nj * 8 + (lane & 3) * 2;
            const float b0 = bias[col], b1 = bias[col + 1];
            if (r0 < M)
                *(float2*)&C[(size_t)r0 * HD + col] =
                    make_float2(acc[mi][nj][0] + b0, acc[mi][nj][1] + b1);
            if (r0 + 8 < M)
                *(float2*)&C[(size_t)(r0 + 8) * HD + col] =
                    make_float2(acc[mi][nj][2] + b0, acc[mi][nj][3] + b1);
        }
    }
}

// ============================================================================
// NT cosine GEMM + FUSED Sinkhorn (validated round 8)
// ============================================================================
__global__ void __launch_bounds__(256) ntexp_sinkhorn_kernel()
{
    extern __shared__ char smem[];
    const int m0 = blockIdx.y * 128, n0 = blockIdx.x * 128;
    const int tid = threadIdx.x, lane = tid & 31, wid = tid >> 5;

    float acc[4][4][4] = {};
    mma_mainloop(g_qh, g_ql, g_kh, g_kl, m0, MQ - 1, n0, smem, acc, tid, lane, wid);
    __syncthreads();

    float* st = (float*)smem;
    const int wm = (wid >> 2) * 64, wn = (wid & 3) * 32;
#pragma unroll
    for (int mi = 0; mi < 4; mi++) {
        const int rr0 = wm + mi * 16 + (lane >> 2);
        const float ai0 = g_qinv[m0 + rr0] * OT_INV_EPS;
        const float ai1 = g_qinv[m0 + rr0 + 8] * OT_INV_EPS;
#pragma unroll
        for (int nj = 0; nj < 4; nj++) {
            const int cl = wn + nj * 8 + (lane & 3) * 2;
            const float b0 = g_kinv[n0 + cl], b1 = g_kinv[n0 + cl + 1];
            const int tj = cl >> 5, j = cl & 31;
            {
                const int ti = rr0 >> 5, i = rr0 & 31;
                float* p = st + (ti * 4 + tj) * 1056 + i * 33 + j;
                p[0] = __expf(acc[mi][nj][0] * ai0 * b0);
                p[1] = __expf(acc[mi][nj][1] * ai0 * b1);
            }
            {
                const int rr1 = rr0 + 8;
                const int ti = rr1 >> 5, i = rr1 & 31;
                float* p = st + (ti * 4 + tj) * 1056 + i * 33 + j;
                p[0] = __expf(acc[mi][nj][2] * ai1 * b0);
                p[1] = __expf(acc[mi][nj][3] * ai1 * b1);
            }
        }
    }
    __syncthreads();

#pragma unroll 1
    for (int tt = 0; tt < 2; tt++) {
        const int t = wid + tt * 8;
        const int ti = t >> 2, tj = t & 3;
        const float* S = st + t * 1056;
        float Q[32], QT[32];
#pragma unroll
        for (int j = 0; j < 32; j++) Q[j]  = S[lane * 33 + j];
#pragma unroll
        for (int j = 0; j < 32; j++) QT[j] = S[j * 33 + lane];
        float v_all[32];
#pragma unroll
        for (int j = 0; j < 32; j++) v_all[j] = 1.0f;
#pragma unroll 1
        for (int it = 0; it < 10; it++) {
            float s = 0.f;
#pragma unroll
            for (int j = 0; j < 32; j++) s = fmaf(Q[j], v_all[j], s);
            const float u = __fdividef(1.0f, s);
#pragma unroll
            for (int j = 0; j < 32; j++) v_all[j] = __shfl_sync(0xffffffffu, u, j);
            float s2 = 0.f;
#pragma unroll
            for (int j = 0; j < 32; j++) s2 = fmaf(QT[j], v_all[j], s2);
            const float v = __fdividef(1.0f, s2);
#pragma unroll
            for (int j = 0; j < 32; j++) v_all[j] = __shfl_sync(0xffffffffu, v, j);
        }
        float n2 = 0.f;
#pragma unroll
        for (int j = 0; j < 32; j++) {
            Q[j] *= v_all[j];
            n2 = fmaf(Q[j], Q[j], n2);
        }
        const float sc = __fdividef(1.0f, fmaxf(sqrtf(n2), 1e-12f));
        const int tileg = (m0 / 32 + ti) * 64 + (n0 / 32 + tj);
        float* dst = g_Tp + (size_t)tileg * 1024 + lane * 32;
#pragma unroll
        for (int p = 0; p < 8; p++)
            *(float4*)&dst[p * 4] = make_float4(Q[p*4] * sc, Q[p*4+1] * sc,
                                                Q[p*4+2] * sc, Q[p*4+3] * sc);
    }
}

// ============================================================================
// row L2-norm inverse + bf16 hi/lo of q,k (validated round 8)
// ============================================================================
__global__ void rownorm_convert_kernel()
{
    int row = blockIdx.x * 8 + (threadIdx.x >> 5);
    int lane = threadIdx.x & 31;
    const float* x; float* inv; bf16 *hp, *lp;
    if (row < MQ) {
        x = g_q + (size_t)row * HD; inv = g_qinv + row;
        hp = g_qh + (size_t)row * HD; lp = g_ql + (size_t)row * HD;
    } else {
        int r2 = row - MQ;
        x = g_k + (size_t)r2 * HD; inv = g_kinv + r2;
        hp = g_kh + (size_t)r2 * HD; lp = g_kl + (size_t)r2 * HD;
    }
    float s = 0.f;
#pragma unroll
    for (int p = 0; p < 6; p++) {
        const int d = lane * 4 + p * 128;
        float4 v4 = *(const float4*)&x[d];
        s += v4.x * v4.x + v4.y * v4.y + v4.z * v4.z + v4.w * v4.w;
        uint2 h, l;
        split4(v4, h, l);
        *(uint2*)&hp[d] = h;
        *(uint2*)&lp[d] = l;
    }
    s = warp_sum(s);
    if (lane == 0) *inv = 1.0f / fmaxf(sqrtf(s), 1e-8f);
}

// ============================================================================
// fused attend + LN1 + softpool + LN2 + scores (round-8 proven version:
// FFMA2 T@v, v streamed from L2, 2 CTAs/SM)
// ============================================================================
__global__ void __launch_bounds__(256, 2) attend_kernel(
    const float* __restrict__ Tp, const float* __restrict__ q,
    const float* __restrict__ v, const float* __restrict__ ecls,
    const float* __restrict__ entity_cls, const float* __restrict__ mention_cls,
    const float* __restrict__ ln1_g, const float* __restrict__ ln1_b,
    const float* __restrict__ Wsp, const float* __restrict__ bsp,
    const float* __restrict__ ln2_g, const float* __restrict__ ln2_b,
    float* __restrict__ out)
{
    extern __shared__ float sm[];
    float* satt  = sm;             // 24576
    float* sTt   = satt + 24576;   // 1152
    float* sWsp  = sTt + 1152;     // 768
    float* spool = sWsp + 768;     // 768
    float* sS    = spool + 768;    // 32
    float* sW    = sS + 32;        // 32
    float* sred  = sW + 32;        // 64

    const int a = blockIdx.y, b = blockIdx.x;
    const int tid = threadIdx.x, lane = tid & 31, wid = tid >> 5;

    const float* Tb = Tp + (size_t)(a * 64 + b) * 1024;
    for (int t = tid; t < 1024; t += 256) {
        int i = t >> 5, j = t & 31;
        sTt[j * 36 + i] = Tb[t];
    }
    for (int t = tid; t < 768; t += 256) sWsp[t] = Wsp[t];
    __syncthreads();

    {
        const int i0 = (wid & 3) * 8;
        const int dbase0 = (wid >> 2) * 384 + lane * 4;
        const float* qa = q + (size_t)(a * 32) * HD;
        const float* vb = v + (size_t)b * 32 * HD;
#pragma unroll 1
        for (int c = 0; c < 3; c++) {
            const int d = dbase0 + c * 128;
            u64 acc[8][2];
#pragma unroll
            for (int ii = 0; ii < 8; ii++) {
                ulonglong2 qv = *(const ulonglong2*)&qa[(i0 + ii) * HD + d];
                acc[ii][0] = qv.x; acc[ii][1] = qv.y;
            }
#pragma unroll 8
            for (int j = 0; j < 32; j++) {
                const ulonglong2 vv = *(const ulonglong2*)&vb[(size_t)j * HD + d];
                float4 t0 = *(const float4*)&sTt[j * 36 + i0];
                float4 t1 = *(const float4*)&sTt[j * 36 + i0 + 4];
                u64 td[8] = {dup2(t0.x), dup2(t0.y), dup2(t0.z), dup2(t0.w),
                             dup2(t1.x), dup2(t1.y), dup2(t1.z), dup2(t1.w)};
#pragma unroll
                for (int ii = 0; ii < 8; ii++) {
                    fma2(acc[ii][0], td[ii], vv.x);
                    fma2(acc[ii][1], td[ii], vv.y);
                }
            }
#pragma unroll
            for (int ii = 0; ii < 8; ii++) {
                ulonglong2 o; o.x = acc[ii][0]; o.y = acc[ii][1];
                *(ulonglong2*)&satt[(i0 + ii) * HD + d] = o;
            }
        }
    }
    __syncthreads();

    const float bsp0 = bsp[0];
#pragma unroll 1
    for (int rr = 0; rr < 4; rr++) {
        const int i = wid + rr * 8;
        float* row = &satt[i * HD];
        float s = 0.f, sq = 0.f;
#pragma unroll
        for (int p = 0; p < 6; p++) {
            float4 x = *(float4*)&row[lane * 4 + p * 128];
            s += x.x + x.y + x.z + x.w;
            sq += x.x * x.x + x.y * x.y + x.z * x.z + x.w * x.w;
        }
        s = warp_sum(s); sq = warp_sum(sq);
        const float mean = s * INV768;
        const float var = sq * INV768 - mean * mean;
        const float rstd = rsqrtf(var + 1e-5f);
        float sc = 0.f;
#pragma unroll
        for (int p = 0; p < 6; p++) {
            const int d = lane * 4 + p * 128;
            float4 x  = *(float4*)&row[d];
            float4 g  = *(const float4*)&ln1_g[d];
            float4 bb = *(const float4*)&ln1_b[d];
            float4 w4 = *(const float4*)&sWsp[d];
            float4 y;
            y.x = (x.x - mean) * rstd * g.x + bb.x;
            y.y = (x.y - mean) * rstd * g.y + bb.y;
            y.z = (x.z - mean) * rstd * g.z + bb.z;
            y.w = (x.w - mean) * rstd * g.w + bb.w;
            *(float4*)&row[d] = y;
            sc += y.x * w4.x + y.y * w4.y + y.z * w4.z + y.w * w4.w;
        }
        sc = warp_sum(sc);
        if (lane == 0) sS[i] = sc + bsp0;
    }
    __syncthreads();

    if (wid == 0) {
        float sval = sS[lane];
        float mx = warp_max(sval);
        float e = expf(sval - mx);
        float sum = warp_sum(e);
        sW[lane] = e / sum;
    }
    __syncthreads();

    for (int d = tid; d < HD; d += 256) {
        float p = 0.f;
#pragma unroll
        for (int i = 0; i < 32; i++) p = fmaf(sW[i], satt[i * HD + d], p);
        spool[d] = p;
    }
    __syncthreads();

    float s = 0.f, sq = 0.f;
    for (int d = tid; d < HD; d += 256) {
        float x = spool[d];
        s += x; sq += x * x;
    }
    s = warp_sum(s); sq = warp_sum(sq);
    if (lane == 0) { sred[wid] = s; sred[8 + wid] = sq; }
    __syncthreads();
    if (tid == 0) {
        float ts = 0.f, tq = 0.f;
#pragma unroll
        for (int w = 0; w < 8; w++) { ts += sred[w]; tq += sred[8 + w]; }
        sred[16] = ts; sred[17] = tq;
    }
    __syncthreads();
    const float mean2 = sred[16] * INV768;
    const float var2 = sred[17] * INV768 - mean2 * mean2;
    const float rstd2 = rsqrtf(var2 + 1e-5f);

    const float* ea  = ecls + (size_t)a * HD;
    const float* eca = entity_cls + (size_t)a * HD;
    const float* mcb = mention_cls + (size_t)b * HD;
    float g2l = 0.f, g2g = 0.f;
    for (int d = tid; d < HD; d += 256) {
        float ctx = (spool[d] - mean2) * rstd2 * ln2_g[d] + ln2_b[d];
        g2l = fmaf(ea[d], ctx, g2l);
        g2g = fmaf(eca[d], mcb[d], g2g);
    }
    g2l = warp_sum(g2l); g2g = warp_sum(g2g);
    __syncthreads();
    if (lane == 0) { sred[wid] = g2l; sred[8 + wid] = g2g; }
    __syncthreads();
    if (tid == 0) {
        float tl = 0.f, tg = 0.f;
#pragma unroll
        for (int w = 0; w < 8; w++) { tl += sred[w]; tg += sred[8 + w]; }
        out[b * NA + a] = 0.5f * (tl + tg);
    }
}

// ---------------------------------------------------------------------------
extern "C" void kernel_launch(void* const* d_in, const int* in_sizes, int n_in,
                              void* d_out, int out_size)
{
    const float* entity_cls     = (const float*)d_in[0];
    const float* entity_tokens  = (const float*)d_in[1];
    const float* mention_cls    = (const float*)d_in[2];
    const float* mention_tokens = (const float*)d_in[3];
    const float* Wq   = (const float*)d_in[4];
    const float* bq   = (const float*)d_in[5];
    const float* Wk   = (const float*)d_in[6];
    const float* bk   = (const float*)d_in[7];
    const float* Wv   = (const float*)d_in[8];
    const float* bv   = (const float*)d_in[9];
    const float* ln1g = (const float*)d_in[10];
    const float* ln1b = (const float*)d_in[11];
    const float* Wcls = (const float*)d_in[12];
    const float* bcls = (const float*)d_in[13];
    const float* Wsp  = (const float*)d_in[14];
    const float* bsp  = (const float*)d_in[15];
    const float* ln2g = (const float*)d_in[16];
    const float* ln2b = (const float*)d_in[17];
    float* out = (float*)d_out;

    float *pq, *pv, *pecls, *pTp;
    cudaGetSymbolAddress((void**)&pq,    g_q);
    cudaGetSymbolAddress((void**)&pv,    g_v);
    cudaGetSymbolAddress((void**)&pecls, g_ecls);
    cudaGetSymbolAddress((void**)&pTp,   g_Tp);

    split_inputs_kernel<<<dim3(1536, 1, 3), 256>>>(entity_tokens, mention_tokens, entity_cls);
    wtrans_kernel<<<dim3(12, 12, 4), 256>>>(Wq, Wk, Wv, Wcls);

    cudaFuncSetAttribute(proj_mma_kernel, cudaFuncAttributeMaxDynamicSharedMemorySize, SMEM_MMA);
    proj_mma_kernel<<<dim3(6, 41), 256, SMEM_MMA>>>(bq, bk, bv, bcls);

    rownorm_convert_kernel<<<(MQ + MKV) / 8, 256>>>();

    cudaFuncSetAttribute(ntexp_sinkhorn_kernel, cudaFuncAttributeMaxDynamicSharedMemorySize, SMEM_MMA);
    ntexp_sinkhorn_kernel<<<dim3(16, 8), 256, SMEM_MMA>>>();

    const int smem_bytes = (24576 + 1152 + 768 + 768 + 32 + 32 + 64) * 4;
    cudaFuncSetAttribute(attend_kernel, cudaFuncAttributeMaxDynamicSharedMemorySize, smem_bytes);
    attend_kernel<<<dim3(BB, NA), 256, smem_bytes>>>(
        pTp, pq, pv, pecls, entity_cls, mention_cls,
        ln1g, ln1b, Wsp, bsp, ln2g, ln2b, out);
}